// round 14
// baseline (speedup 1.0000x reference)
#include <cuda_runtime.h>
#include <cuda_fp16.h>
#include <cstdint>

#define TOK    262144          // 4*256*256 tokens
#define CDIM   192

// ---------------- scratch (device globals; no allocation) ----------------
__device__ __half g_ln  [(size_t)TOK * 192];   // LN1 (window layout) then LN2 (token layout)
__device__ __half g_big [(size_t)TOK * 768];   // qkv (576 wide) then fc1 activation (768 wide)
__device__ __half g_ow  [(size_t)TOK * 192];   // attention output, window layout
__device__ __half g_xo  [(size_t)TOK * 192];   // post-attention residual, token layout (fp16)
__device__ __half g_wqkv_h[192 * 576];
__device__ __half g_wproj_h[192 * 192];
__device__ __half g_wfc1_h[192 * 768];
__device__ __half g_wfc2_h[768 * 192];

// ---------------- cp.async helpers ----------------
__device__ __forceinline__ void cp_async16(void* smem_dst, const void* gmem_src) {
    uint32_t s = (uint32_t)__cvta_generic_to_shared(smem_dst);
    asm volatile("cp.async.cg.shared.global [%0], [%1], 16;\n" :: "r"(s), "l"(gmem_src));
}
__device__ __forceinline__ void cp_commit() {
    asm volatile("cp.async.commit_group;\n" ::: "memory");
}
template<int N>
__device__ __forceinline__ void cp_wait() {
    asm volatile("cp.async.wait_group %0;\n" :: "n"(N) : "memory");
}

// ---------------- mma.sync / ldmatrix helpers ----------------
__device__ __forceinline__ void mma16816(float* c, const uint32_t* a, const uint32_t* b) {
    asm volatile("mma.sync.aligned.m16n8k16.row.col.f32.f16.f16.f32 "
                 "{%0,%1,%2,%3}, {%4,%5,%6,%7}, {%8,%9}, {%0,%1,%2,%3};"
                 : "+f"(c[0]), "+f"(c[1]), "+f"(c[2]), "+f"(c[3])
                 : "r"(a[0]), "r"(a[1]), "r"(a[2]), "r"(a[3]), "r"(b[0]), "r"(b[1]));
}
__device__ __forceinline__ void ldsm4(uint32_t* d, uint32_t addr) {
    asm volatile("ldmatrix.sync.aligned.m8n8.x4.shared.b16 {%0,%1,%2,%3}, [%4];"
                 : "=r"(d[0]), "=r"(d[1]), "=r"(d[2]), "=r"(d[3]) : "r"(addr));
}
__device__ __forceinline__ void ldsm4t(uint32_t* d, uint32_t addr) {
    asm volatile("ldmatrix.sync.aligned.m8n8.x4.trans.shared.b16 {%0,%1,%2,%3}, [%4];"
                 : "=r"(d[0]), "=r"(d[1]), "=r"(d[2]), "=r"(d[3]) : "r"(addr));
}
__device__ __forceinline__ uint32_t packh2(float lo, float hi) {
    __half2 h = __floats2half2_rn(lo, hi);
    return *(uint32_t*)&h;
}

// ---------------- fused fp32 -> fp16 conversion of all four weights ----------------
__global__ __launch_bounds__(256) void f2h_all_kernel(const float* __restrict__ w0, __half* o0, int n0,
                                                      const float* __restrict__ w1, __half* o1, int n1,
                                                      const float* __restrict__ w2, __half* o2, int n2,
                                                      const float* __restrict__ w3, __half* o3, int n3)
{
    int i = blockIdx.x * 256 + threadIdx.x;
    const float* src; __half* dst;
    if (i < n0)                    { src = w0; dst = o0; }
    else if ((i -= n0) < n1)       { src = w1; dst = o1; }
    else if ((i -= n1) < n2)       { src = w2; dst = o2; }
    else if ((i -= n2) < n3)       { src = w3; dst = o3; }
    else return;
    float4 v = *(const float4*)(src + (size_t)i * 4);
    *(uint2*)(dst + (size_t)i * 4) = make_uint2(packh2(v.x, v.y), packh2(v.z, v.w));
}

// ---------------- LayerNorm (one warp per token), templated input, fp16 output ----------------
template<bool WINDOW_DST, typename T>
__global__ __launch_bounds__(256) void ln_kernel(const T* __restrict__ x,
                                                 const float* __restrict__ g,
                                                 const float* __restrict__ b,
                                                 __half* __restrict__ out)
{
    int tok  = blockIdx.x * (blockDim.x >> 5) + (threadIdx.x >> 5);
    int lane = threadIdx.x & 31;
    const T* row = x + (size_t)tok * CDIM;
    float v[6];
    float s = 0.f, s2 = 0.f;
#pragma unroll
    for (int k = 0; k < 6; k++) {
        v[k] = (float)row[lane + 32 * k];
        s  += v[k];
        s2 += v[k] * v[k];
    }
#pragma unroll
    for (int o = 16; o > 0; o >>= 1) {
        s  += __shfl_xor_sync(0xffffffffu, s,  o);
        s2 += __shfl_xor_sync(0xffffffffu, s2, o);
    }
    float mean = s * (1.f / 192.f);
    float var  = s2 * (1.f / 192.f) - mean * mean;
    float inv  = rsqrtf(var + 1e-5f);

    size_t drow;
    if (WINDOW_DST) {
        int bb  = tok >> 16;
        int rem = tok & 65535;
        int h   = rem >> 8;
        int w   = rem & 255;
        int win = (bb << 10) + ((h >> 3) << 5) + (w >> 3);
        int n   = ((h & 7) << 3) + (w & 7);
        drow = (size_t)win * 64 + n;
    } else {
        drow = (size_t)tok;
    }
    __half* orow = out + drow * CDIM;
#pragma unroll
    for (int k = 0; k < 6; k++) {
        int c = lane + 32 * k;
        orow[c] = __float2half_rn((v[k] - mean) * inv * g[c] + b[c]);
    }
}

// ---------------- GEMM: mma.sync m16n8k16, 128x96 tile, 256 thr, 3-stage, 2 CTAs/SM ----------------
// Register-direct epilogue: no smem C staging, no epilogue barriers.
#define GBM 128
#define GBN 96
#define GBK 64
#define NTHR 256

#define ALDH 72                   // 64 + 8 halves pad (row = 144 B, 16B-aligned)
#define BLDH 104                  // 96 + 8 halves pad (row = 208 B, 16B-aligned)
#define SA_HALF (GBM * ALDH)      // 9216 halves
#define SB_HALF (GBK * BLDH)      // 6656 halves
#define STAGE_HALF (SA_HALF + SB_HALF)
#define GEMM_DYN (3 * STAGE_HALF * 2)   // 95232 B

enum { EPI_QKV = 0, EPI_PROJ = 1, EPI_FC1 = 2, EPI_FC2 = 3 };

// A: [M][KDIM] half row-major; B: [KDIM][NDIM] half row-major.
// Warp grid 4(rows) x 2(cols); warp tile 32x48 = 2 m-frags x 6 n-frags.
template<int KDIM, int NDIM, int EPI>
__global__ __launch_bounds__(NTHR, 2) void gemm_kernel(const __half* __restrict__ A,
                                                       const __half* __restrict__ B,
                                                       const float* __restrict__ bias,
                                                       const void* __restrict__ res_v,
                                                       void* __restrict__ out_v)
{
    extern __shared__ char dynsm[];
    __half* sbase = (__half*)dynsm;

    const int bn   = blockIdx.x;
    const int bm   = blockIdx.y;
    const int tid  = threadIdx.x;
    const int warp = tid >> 5;
    const int lane = tid & 31;
    const int wr   = warp >> 1;   // 0..3 : 32-row group
    const int wc   = warp & 1;    // 0..1 : 48-col group
    const int gid  = lane >> 2;   // 0..7
    const int tig  = lane & 3;    // 0..3

    const __half* Abase = A + (size_t)(bm * GBM) * KDIM;
    const __half* Bbase = B + (size_t)bn * GBN;

    // per-lane ldmatrix offsets (halves)
    const int a_off = (lane & 15) * ALDH + (lane >> 4) * 8;
    const int b_off = (lane & 15) * BLDH + (lane >> 4) * 8;

    float acc[2][6][4];
#pragma unroll
    for (int i = 0; i < 2; i++)
#pragma unroll
        for (int j = 0; j < 6; j++)
#pragma unroll
            for (int q = 0; q < 4; q++) acc[i][j][q] = 0.f;

    auto issue_stage = [&](int st, int k0) {
        __half* sa = sbase + st * STAGE_HALF;
        __half* sb = sa + SA_HALF;
#pragma unroll
        for (int s = 0; s < 4; s++) {
            int line = tid + s * NTHR;
            int r = line >> 3, c8 = line & 7;
            cp_async16(&sa[r * ALDH + c8 * 8],
                       Abase + (size_t)r * KDIM + k0 + c8 * 8);
        }
#pragma unroll
        for (int s = 0; s < 3; s++) {
            int line = tid + s * NTHR;
            int r = line / 12, c8 = line % 12;
            cp_async16(&sb[r * BLDH + c8 * 8],
                       Bbase + (size_t)(k0 + r) * NDIM + c8 * 8);
        }
        cp_commit();
    };

    constexpr int NK = KDIM / GBK;
    issue_stage(0, 0);
    if (NK > 1) issue_stage(1, GBK);

    // Single-barrier mainloop: wait(cur) -> barrier -> issue(kt+2) -> compute(kt).
#pragma unroll 1
    for (int kt = 0; kt < NK; kt++) {
        if (kt + 1 < NK) cp_wait<1>(); else cp_wait<0>();
        __syncthreads();
        if (kt + 2 < NK) issue_stage((kt + 2) % 3, (kt + 2) * GBK);

        const __half* sa = sbase + (kt % 3) * STAGE_HALF;
        const __half* sb = sa + SA_HALF;
        uint32_t sa_u = (uint32_t)__cvta_generic_to_shared(sa);
        uint32_t sb_u = (uint32_t)__cvta_generic_to_shared(sb);

#pragma unroll
        for (int kk = 0; kk < GBK; kk += 16) {
            uint32_t af[2][4];
#pragma unroll
            for (int i = 0; i < 2; i++)
                ldsm4(af[i], sa_u + (uint32_t)(((wr * 32 + i * 16) * ALDH + kk + a_off) * 2));
            uint32_t bf[3][4];
#pragma unroll
            for (int jj = 0; jj < 3; jj++)
                ldsm4t(bf[jj], sb_u + (uint32_t)((kk * BLDH + wc * 48 + jj * 16 + b_off) * 2));
#pragma unroll
            for (int i = 0; i < 2; i++)
#pragma unroll
                for (int j = 0; j < 6; j++)
                    mma16816(acc[i][j], af[i], &bf[j >> 1][(j & 1) * 2]);
        }
    }

    // ---------------- register-direct epilogue ----------------
    // acc[i][j]: rows (wr*32 + i*16 + gid) and (+8); cols (wc*48 + j*8 + tig*2, +1)
    float2 bj[6];
#pragma unroll
    for (int j = 0; j < 6; j++)
        bj[j] = *(const float2*)&bias[bn * GBN + wc * 48 + j * 8 + tig * 2];

#pragma unroll
    for (int i = 0; i < 2; i++) {
#pragma unroll
        for (int h = 0; h < 2; h++) {
            int rloc = wr * 32 + i * 16 + gid + h * 8;
            size_t grow = (size_t)bm * GBM + rloc;

            if constexpr (EPI == EPI_QKV || EPI == EPI_FC1) {
                __half* out = (__half*)out_v;
                __half* orow = out + grow * NDIM + bn * GBN + wc * 48 + tig * 2;
#pragma unroll
                for (int j = 0; j < 6; j++) {
                    float v0 = acc[i][j][h * 2 + 0] + bj[j].x;
                    float v1 = acc[i][j][h * 2 + 1] + bj[j].y;
                    if constexpr (EPI == EPI_FC1) {
                        v0 *= normcdff(v0);
                        v1 *= normcdff(v1);
                    }
                    *(uint32_t*)&orow[j * 8] = packh2(v0, v1);
                }
            } else if constexpr (EPI == EPI_PROJ) {
                __half* out = (__half*)out_v;              // xo fp16 (token order)
                const float* res = (const float*)res_v;    // original x fp32
                int rg  = (int)grow;
                int win = rg >> 6, n = rg & 63;
                int bbi = win >> 10, wrw = win & 1023;
                int hh  = ((wrw >> 5) << 3) + (n >> 3);
                int ww  = ((wrw & 31) << 3) + (n & 7);
                size_t t = ((size_t)bbi << 16) + ((size_t)hh << 8) + (size_t)ww;
                const float* rrow = res + t * CDIM + bn * GBN + wc * 48 + tig * 2;
                __half* orow = out + t * CDIM + bn * GBN + wc * 48 + tig * 2;
#pragma unroll
                for (int j = 0; j < 6; j++) {
                    float2 rr = *(const float2*)&rrow[j * 8];
                    float v0 = acc[i][j][h * 2 + 0] + bj[j].x + rr.x;
                    float v1 = acc[i][j][h * 2 + 1] + bj[j].y + rr.y;
                    *(uint32_t*)&orow[j * 8] = packh2(v0, v1);
                }
            } else {  // EPI_FC2
                float* out = (float*)out_v;
                const __half* res = (const __half*)res_v;  // xo fp16
                const __half* rrow = res + grow * CDIM + bn * GBN + wc * 48 + tig * 2;
                float* orow = out + grow * (size_t)NDIM + bn * GBN + wc * 48 + tig * 2;
#pragma unroll
                for (int j = 0; j < 6; j++) {
                    uint32_t raw = *(const uint32_t*)&rrow[j * 8];
                    float2 rr = __half22float2(*(__half2*)&raw);
                    float2 v;
                    v.x = acc[i][j][h * 2 + 0] + bj[j].x + rr.x;
                    v.y = acc[i][j][h * 2 + 1] + bj[j].y + rr.y;
                    *(float2*)&orow[j * 8] = v;
                }
            }
        }
    }
}

// ---------------- attention: register-softmax mma.sync pipeline (R13, unchanged) ----------------
#define AQLD 72
#define ATTN_DYN (3 * 64 * AQLD * 2)   // 27648 B

__global__ __launch_bounds__(256) void attn_kernel(const __half* __restrict__ qkv,
                                                   __half* __restrict__ o)
{
    extern __shared__ char smraw[];
    __half* qs = (__half*)smraw;
    __half* ks = qs + 64 * AQLD;
    __half* vs = ks + 64 * AQLD;

    const int hp  = blockIdx.x;
    const int win = blockIdx.y;
    const int tid = threadIdx.x;
    const int wid = tid >> 5;
    const int lane = tid & 31;

    const __half* base = qkv + (size_t)win * 36864 + hp * 64;
#pragma unroll
    for (int s = 0; s < 2; s++) {
        int idx = tid + s * 256;
        int r = idx >> 3, c8 = idx & 7;
        const __half* rp = base + (size_t)r * 576 + c8 * 8;
        *(uint4*)&qs[r * AQLD + c8 * 8] = *(const uint4*)(rp);
        *(uint4*)&ks[r * AQLD + c8 * 8] = *(const uint4*)(rp + 192);
        *(uint4*)&vs[r * AQLD + c8 * 8] = *(const uint4*)(rp + 384);
    }
    __syncthreads();

    const int hh    = wid >> 2;
    const int strip = wid & 3;
    const int gid   = lane >> 2;
    const int tig   = lane & 3;
    const int r1    = strip * 16 + gid;
    const int kb    = hh * 32;

    uint32_t aq[2][4];
#pragma unroll
    for (int kt = 0; kt < 2; kt++) {
        int k0 = kb + kt * 16 + tig * 2;
        aq[kt][0] = *(uint32_t*)&qs[r1 * AQLD + k0];
        aq[kt][1] = *(uint32_t*)&qs[(r1 + 8) * AQLD + k0];
        aq[kt][2] = *(uint32_t*)&qs[r1 * AQLD + k0 + 8];
        aq[kt][3] = *(uint32_t*)&qs[(r1 + 8) * AQLD + k0 + 8];
    }

    float sc[8][4];
#pragma unroll
    for (int jt = 0; jt < 8; jt++) { sc[jt][0] = sc[jt][1] = sc[jt][2] = sc[jt][3] = 0.f; }
#pragma unroll
    for (int jt = 0; jt < 8; jt++) {
        int jr = jt * 8 + gid;
#pragma unroll
        for (int kt = 0; kt < 2; kt++) {
            int k0 = kb + kt * 16 + tig * 2;
            uint32_t bf[2];
            bf[0] = *(uint32_t*)&ks[jr * AQLD + k0];
            bf[1] = *(uint32_t*)&ks[jr * AQLD + k0 + 8];
            mma16816(sc[jt], aq[kt], bf);
        }
    }

    const float scale = 0.17677669529663687f;
    float m1 = -1e30f, m2 = -1e30f;
#pragma unroll
    for (int jt = 0; jt < 8; jt++) {
        sc[jt][0] *= scale; sc[jt][1] *= scale; sc[jt][2] *= scale; sc[jt][3] *= scale;
        m1 = fmaxf(m1, fmaxf(sc[jt][0], sc[jt][1]));
        m2 = fmaxf(m2, fmaxf(sc[jt][2], sc[jt][3]));
    }
    m1 = fmaxf(m1, __shfl_xor_sync(0xffffffffu, m1, 1));
    m1 = fmaxf(m1, __shfl_xor_sync(0xffffffffu, m1, 2));
    m2 = fmaxf(m2, __shfl_xor_sync(0xffffffffu, m2, 1));
    m2 = fmaxf(m2, __shfl_xor_sync(0xffffffffu, m2, 2));
    float s1 = 0.f, s2 = 0.f;
#pragma unroll
    for (int jt = 0; jt < 8; jt++) {
        sc[jt][0] = __expf(sc[jt][0] - m1); sc[jt][1] = __expf(sc[jt][1] - m1);
        sc[jt][2] = __expf(sc[jt][2] - m2); sc[jt][3] = __expf(sc[jt][3] - m2);
        s1 += sc[jt][0] + sc[jt][1];
        s2 += sc[jt][2] + sc[jt][3];
    }
    s1 += __shfl_xor_sync(0xffffffffu, s1, 1);
    s1 += __shfl_xor_sync(0xffffffffu, s1, 2);
    s2 += __shfl_xor_sync(0xffffffffu, s2, 1);
    s2 += __shfl_xor_sync(0xffffffffu, s2, 2);
    float i1 = 1.f / s1, i2 = 1.f / s2;

    uint32_t phr1[8], phr2[8];
#pragma unroll
    for (int jt = 0; jt < 8; jt++) {
        phr1[jt] = packh2(sc[jt][0] * i1, sc[jt][1] * i1);
        phr2[jt] = packh2(sc[jt][2] * i2, sc[jt][3] * i2);
    }

    float oc[4][4];
#pragma unroll
    for (int nt = 0; nt < 4; nt++) { oc[nt][0] = oc[nt][1] = oc[nt][2] = oc[nt][3] = 0.f; }
#pragma unroll
    for (int kt = 0; kt < 4; kt++) {
        uint32_t pa[4] = { phr1[2 * kt], phr2[2 * kt], phr1[2 * kt + 1], phr2[2 * kt + 1] };
        int k0 = kt * 16 + tig * 2;
#pragma unroll
        for (int nt = 0; nt < 4; nt++) {
            int d = kb + nt * 8 + gid;
            uint32_t bf[2];
            __half b00 = vs[(size_t)k0 * AQLD + d];
            __half b01 = vs[(size_t)(k0 + 1) * AQLD + d];
            __half b10 = vs[(size_t)(k0 + 8) * AQLD + d];
            __half b11 = vs[(size_t)(k0 + 9) * AQLD + d];
            __half2 h0 = __halves2half2(b00, b01);
            __half2 h1 = __halves2half2(b10, b11);
            bf[0] = *(uint32_t*)&h0;
            bf[1] = *(uint32_t*)&h1;
            mma16816(oc[nt], pa, bf);
        }
    }

    size_t ro1 = (size_t)(win * 64 + r1) * 192 + hp * 64 + kb;
    size_t ro2 = ro1 + (size_t)8 * 192;
#pragma unroll
    for (int nt = 0; nt < 4; nt++) {
        int dc = nt * 8 + tig * 2;
        *(uint32_t*)&o[ro1 + dc] = packh2(oc[nt][0], oc[nt][1]);
        *(uint32_t*)&o[ro2 + dc] = packh2(oc[nt][2], oc[nt][3]);
    }
}

// ---------------- launch ----------------
extern "C" void kernel_launch(void* const* d_in, const int* in_sizes, int n_in,
                              void* d_out, int out_size)
{
    (void)in_sizes; (void)n_in; (void)out_size;
    const float* x      = (const float*)d_in[0];
    const float* g1     = (const float*)d_in[1];
    const float* b1     = (const float*)d_in[2];
    const float* w_qkv  = (const float*)d_in[3];
    const float* b_qkv  = (const float*)d_in[4];
    const float* w_proj = (const float*)d_in[5];
    const float* b_proj = (const float*)d_in[6];
    const float* g2     = (const float*)d_in[7];
    const float* b2     = (const float*)d_in[8];
    const float* w_fc1  = (const float*)d_in[9];
    const float* b_fc1  = (const float*)d_in[10];
    const float* w_fc2  = (const float*)d_in[11];
    const float* b_fc2  = (const float*)d_in[12];
    float* out = (float*)d_out;

    __half *ln, *big, *ow, *xo, *wqkv_h, *wproj_h, *wfc1_h, *wfc2_h;
    cudaGetSymbolAddress((void**)&ln,  g_ln);
    cudaGetSymbolAddress((void**)&big, g_big);
    cudaGetSymbolAddress((void**)&ow,  g_ow);
    cudaGetSymbolAddress((void**)&xo,  g_xo);
    cudaGetSymbolAddress((void**)&wqkv_h, g_wqkv_h);
    cudaGetSymbolAddress((void**)&wproj_h, g_wproj_h);
    cudaGetSymbolAddress((void**)&wfc1_h, g_wfc1_h);
    cudaGetSymbolAddress((void**)&wfc2_h, g_wfc2_h);

    const int SB = (int)GEMM_DYN;
    cudaFuncSetAttribute(gemm_kernel<192, 576, EPI_QKV>,  cudaFuncAttributeMaxDynamicSharedMemorySize, SB);
    cudaFuncSetAttribute(gemm_kernel<192, 192, EPI_PROJ>, cudaFuncAttributeMaxDynamicSharedMemorySize, SB);
    cudaFuncSetAttribute(gemm_kernel<192, 768, EPI_FC1>,  cudaFuncAttributeMaxDynamicSharedMemorySize, SB);
    cudaFuncSetAttribute(gemm_kernel<768, 192, EPI_FC2>,  cudaFuncAttributeMaxDynamicSharedMemorySize, SB);

    // 0. all weights fp32 -> fp16, one launch
    {
        int n0 = 192 * 576 / 4, n1 = 192 * 192 / 4, n2 = 192 * 768 / 4, n3 = 768 * 192 / 4;
        int total = n0 + n1 + n2 + n3;
        f2h_all_kernel<<<(total + 255) / 256, 256>>>(w_qkv, wqkv_h, n0, w_proj, wproj_h, n1,
                                                     w_fc1, wfc1_h, n2, w_fc2, wfc2_h, n3);
    }

    // 1. LN1 + window partition (fp32 in, fp16 out)
    ln_kernel<true, float><<<TOK / 8, 256>>>(x, g1, b1, ln);
    // 2. QKV GEMM: 6 column blocks of 96 (fp16 out)
    gemm_kernel<192, 576, EPI_QKV><<<dim3(6, TOK / GBM), NTHR, SB>>>(ln, wqkv_h, b_qkv, nullptr, big);
    // 3. attention per (head-pair, window): register softmax pipeline
    attn_kernel<<<dim3(3, 4096), 256, ATTN_DYN>>>(big, ow);
    // 4. proj GEMM + window unpartition + residual x -> xo (fp16)
    gemm_kernel<192, 192, EPI_PROJ><<<dim3(2, TOK / GBM), NTHR, SB>>>(ow, wproj_h, b_proj, x, xo);
    // 5. LN2 (fp16 in, fp16 out)
    ln_kernel<false, __half><<<TOK / 8, 256>>>(xo, g2, b2, ln);
    // 6. FC1 GEMM + exact GELU (fp16 out)
    gemm_kernel<192, 768, EPI_FC1><<<dim3(8, TOK / GBM), NTHR, SB>>>(ln, wfc1_h, b_fc1, nullptr, big);
    // 7. FC2 GEMM + residual xo (fp16) -> out (fp32)
    gemm_kernel<768, 192, EPI_FC2><<<dim3(2, TOK / GBM), NTHR, SB>>>(big, wfc2_h, b_fc2, xo, out);
}

// round 15
// speedup vs baseline: 1.0292x; 1.0292x over previous
#include <cuda_runtime.h>
#include <cuda_fp16.h>
#include <mma.h>
#include <cstdint>

using namespace nvcuda;

#define TOK    262144          // 4*256*256 tokens
#define CDIM   192

// ---------------- scratch (device globals; no allocation) ----------------
__device__ __half g_ln  [(size_t)TOK * 192];   // LN1 (window layout) then LN2 (token layout)
__device__ __half g_big [(size_t)TOK * 768];   // qkv (576 wide) then fc1 activation (768 wide)
__device__ __half g_ow  [(size_t)TOK * 192];   // attention output, window layout
__device__ __half g_xo  [(size_t)TOK * 192];   // post-attention residual, token layout (fp16)
__device__ __half g_wqkv_h[192 * 576];
__device__ __half g_wproj_h[192 * 192];
__device__ __half g_wfc1_h[192 * 768];
__device__ __half g_wfc2_h[768 * 192];

// ---------------- cp.async helpers ----------------
__device__ __forceinline__ void cp_async16(void* smem_dst, const void* gmem_src) {
    uint32_t s = (uint32_t)__cvta_generic_to_shared(smem_dst);
    asm volatile("cp.async.cg.shared.global [%0], [%1], 16;\n" :: "r"(s), "l"(gmem_src));
}
__device__ __forceinline__ void cp_commit() {
    asm volatile("cp.async.commit_group;\n" ::: "memory");
}
template<int N>
__device__ __forceinline__ void cp_wait() {
    asm volatile("cp.async.wait_group %0;\n" :: "n"(N) : "memory");
}

// ---------------- mma.sync / ldmatrix helpers ----------------
__device__ __forceinline__ void mma16816(float* c, const uint32_t* a, const uint32_t* b) {
    asm volatile("mma.sync.aligned.m16n8k16.row.col.f32.f16.f16.f32 "
                 "{%0,%1,%2,%3}, {%4,%5,%6,%7}, {%8,%9}, {%0,%1,%2,%3};"
                 : "+f"(c[0]), "+f"(c[1]), "+f"(c[2]), "+f"(c[3])
                 : "r"(a[0]), "r"(a[1]), "r"(a[2]), "r"(a[3]), "r"(b[0]), "r"(b[1]));
}
__device__ __forceinline__ void ldsm4(uint32_t* d, uint32_t addr) {
    asm volatile("ldmatrix.sync.aligned.m8n8.x4.shared.b16 {%0,%1,%2,%3}, [%4];"
                 : "=r"(d[0]), "=r"(d[1]), "=r"(d[2]), "=r"(d[3]) : "r"(addr));
}
__device__ __forceinline__ void ldsm4t(uint32_t* d, uint32_t addr) {
    asm volatile("ldmatrix.sync.aligned.m8n8.x4.trans.shared.b16 {%0,%1,%2,%3}, [%4];"
                 : "=r"(d[0]), "=r"(d[1]), "=r"(d[2]), "=r"(d[3]) : "r"(addr));
}
__device__ __forceinline__ uint32_t packh2(float lo, float hi) {
    __half2 h = __floats2half2_rn(lo, hi);
    return *(uint32_t*)&h;
}

// ---------------- fused fp32 -> fp16 conversion of all four weights ----------------
__global__ __launch_bounds__(256) void f2h_all_kernel(const float* __restrict__ w0, __half* o0, int n0,
                                                      const float* __restrict__ w1, __half* o1, int n1,
                                                      const float* __restrict__ w2, __half* o2, int n2,
                                                      const float* __restrict__ w3, __half* o3, int n3)
{
    int i = blockIdx.x * 256 + threadIdx.x;
    const float* src; __half* dst;
    if (i < n0)                    { src = w0; dst = o0; }
    else if ((i -= n0) < n1)       { src = w1; dst = o1; }
    else if ((i -= n1) < n2)       { src = w2; dst = o2; }
    else if ((i -= n2) < n3)       { src = w3; dst = o3; }
    else return;
    float4 v = *(const float4*)(src + (size_t)i * 4);
    *(uint2*)(dst + (size_t)i * 4) = make_uint2(packh2(v.x, v.y), packh2(v.z, v.w));
}

// ---------------- LayerNorm (one warp per token), templated input, fp16 output ----------------
template<bool WINDOW_DST, typename T>
__global__ __launch_bounds__(256) void ln_kernel(const T* __restrict__ x,
                                                 const float* __restrict__ g,
                                                 const float* __restrict__ b,
                                                 __half* __restrict__ out)
{
    int tok  = blockIdx.x * (blockDim.x >> 5) + (threadIdx.x >> 5);
    int lane = threadIdx.x & 31;
    const T* row = x + (size_t)tok * CDIM;
    float v[6];
    float s = 0.f, s2 = 0.f;
#pragma unroll
    for (int k = 0; k < 6; k++) {
        v[k] = (float)row[lane + 32 * k];
        s  += v[k];
        s2 += v[k] * v[k];
    }
#pragma unroll
    for (int o = 16; o > 0; o >>= 1) {
        s  += __shfl_xor_sync(0xffffffffu, s,  o);
        s2 += __shfl_xor_sync(0xffffffffu, s2, o);
    }
    float mean = s * (1.f / 192.f);
    float var  = s2 * (1.f / 192.f) - mean * mean;
    float inv  = rsqrtf(var + 1e-5f);

    size_t drow;
    if (WINDOW_DST) {
        int bb  = tok >> 16;
        int rem = tok & 65535;
        int h   = rem >> 8;
        int w   = rem & 255;
        int win = (bb << 10) + ((h >> 3) << 5) + (w >> 3);
        int n   = ((h & 7) << 3) + (w & 7);
        drow = (size_t)win * 64 + n;
    } else {
        drow = (size_t)tok;
    }
    __half* orow = out + drow * CDIM;
#pragma unroll
    for (int k = 0; k < 6; k++) {
        int c = lane + 32 * k;
        orow[c] = __float2half_rn((v[k] - mean) * inv * g[c] + b[c]);
    }
}

// ---------------- GEMM: fp16 wmma, 128x96 tile, 256 thr, 3-stage, 2 CTAs/SM (R13) ----------------
#define GBM 128
#define GBN 96
#define GBK 64
#define NTHR 256

#define ALDH 72                   // 64 + 8 halves pad
#define BLDH 104                  // 96 + 8 halves pad
#define SA_HALF (GBM * ALDH)      // 9216 halves
#define SB_HALF (GBK * BLDH)      // 6656 halves
#define STAGE_HALF (SA_HALF + SB_HALF)
#define GEMM_DYN (3 * STAGE_HALF * 2)   // 95232 B; epilogue csm 128*100*4 = 51200 fits
#define CLD 100

enum { EPI_QKV = 0, EPI_PROJ = 1, EPI_FC1 = 2, EPI_FC2 = 3 };

// A: [M][KDIM] half row-major; B: [KDIM][NDIM] half row-major.
// EPI_PROJ: res = x (fp32), out = xo (fp16, token scatter).
// EPI_FC2:  res = xo (fp16), out = final (fp32).
template<int KDIM, int NDIM, int EPI>
__global__ __launch_bounds__(NTHR, 2) void gemm_kernel(const __half* __restrict__ A,
                                                       const __half* __restrict__ B,
                                                       const float* __restrict__ bias,
                                                       const void* __restrict__ res_v,
                                                       void* __restrict__ out_v)
{
    extern __shared__ char dynsm[];
    __half* sbase = (__half*)dynsm;
    float*  csm   = (float*)dynsm;

    const int bn   = blockIdx.x;
    const int bm   = blockIdx.y;
    const int tid  = threadIdx.x;
    const int warp = tid >> 5;
    const int wr   = warp >> 1;   // 0..3 : 32-row group
    const int wc   = warp & 1;    // 0..1 : 48-col group

    const __half* Abase = A + (size_t)(bm * GBM) * KDIM;
    const __half* Bbase = B + (size_t)bn * GBN;

    wmma::fragment<wmma::accumulator, 16, 16, 16, float> acc[2][3];
#pragma unroll
    for (int i = 0; i < 2; i++)
#pragma unroll
        for (int j = 0; j < 3; j++) wmma::fill_fragment(acc[i][j], 0.f);

    auto issue_stage = [&](int st, int k0) {
        __half* sa = sbase + st * STAGE_HALF;
        __half* sb = sa + SA_HALF;
#pragma unroll
        for (int s = 0; s < 4; s++) {
            int line = tid + s * NTHR;
            int r = line >> 3, c8 = line & 7;
            cp_async16(&sa[r * ALDH + c8 * 8],
                       Abase + (size_t)r * KDIM + k0 + c8 * 8);
        }
#pragma unroll
        for (int s = 0; s < 3; s++) {
            int line = tid + s * NTHR;
            int r = line / 12, c8 = line % 12;
            cp_async16(&sb[r * BLDH + c8 * 8],
                       Bbase + (size_t)(k0 + r) * NDIM + c8 * 8);
        }
        cp_commit();
    };

    constexpr int NK = KDIM / GBK;
    issue_stage(0, 0);
    if (NK > 1) issue_stage(1, GBK);

    // Single-barrier mainloop: wait(cur) -> barrier -> issue(kt+2) -> compute(kt).
#pragma unroll 1
    for (int kt = 0; kt < NK; kt++) {
        if (kt + 1 < NK) cp_wait<1>(); else cp_wait<0>();
        __syncthreads();
        if (kt + 2 < NK) issue_stage((kt + 2) % 3, (kt + 2) * GBK);

        const __half* sa = sbase + (kt % 3) * STAGE_HALF;
        const __half* sb = sa + SA_HALF;
#pragma unroll
        for (int kk = 0; kk < GBK; kk += 16) {
            wmma::fragment<wmma::matrix_a, 16, 16, 16, __half, wmma::row_major> af[2];
            wmma::fragment<wmma::matrix_b, 16, 16, 16, __half, wmma::row_major> bf[3];
#pragma unroll
            for (int i = 0; i < 2; i++)
                wmma::load_matrix_sync(af[i], &sa[(wr * 32 + i * 16) * ALDH + kk], ALDH);
#pragma unroll
            for (int j = 0; j < 3; j++)
                wmma::load_matrix_sync(bf[j], &sb[kk * BLDH + wc * 48 + j * 16], BLDH);
#pragma unroll
            for (int i = 0; i < 2; i++)
#pragma unroll
                for (int j = 0; j < 3; j++)
                    wmma::mma_sync(acc[i][j], af[i], bf[j], acc[i][j]);
        }
    }
    __syncthreads();   // all compute done before csm overwrites stage buffers

#pragma unroll
    for (int i = 0; i < 2; i++)
#pragma unroll
        for (int j = 0; j < 3; j++)
            wmma::store_matrix_sync(&csm[(wr * 32 + i * 16) * CLD + wc * 48 + j * 16],
                                    acc[i][j], CLD, wmma::mem_row_major);
    __syncthreads();

    // epilogue: 128x96 = 3072 float4-groups, 12 per thread
#pragma unroll
    for (int e = tid; e < GBM * (GBN / 4); e += NTHR) {
        int r  = e / 24;
        int c4 = e % 24;
        int gcol = bn * GBN + c4 * 4;
        size_t grow = (size_t)bm * GBM + r;
        float4 v  = *(float4*)&csm[r * CLD + c4 * 4];
        float4 bb = *(const float4*)&bias[gcol];
        v.x += bb.x; v.y += bb.y; v.z += bb.z; v.w += bb.w;

        if constexpr (EPI == EPI_QKV) {
            __half* out = (__half*)out_v;
            *(uint2*)&out[grow * NDIM + gcol] = make_uint2(packh2(v.x, v.y), packh2(v.z, v.w));
        } else if constexpr (EPI == EPI_PROJ) {
            __half* out = (__half*)out_v;              // xo fp16
            const float* res = (const float*)res_v;    // original x fp32
            int rg  = (int)grow;
            int win = rg >> 6, n = rg & 63;
            int bbi = win >> 10, wrw = win & 1023;
            int h   = ((wrw >> 5) << 3) + (n >> 3);
            int w   = ((wrw & 31) << 3) + (n & 7);
            size_t t = ((size_t)bbi << 16) + ((size_t)h << 8) + (size_t)w;
            float4 rr = *(const float4*)&res[t * CDIM + gcol];
            v.x += rr.x; v.y += rr.y; v.z += rr.z; v.w += rr.w;
            *(uint2*)&out[t * CDIM + gcol] = make_uint2(packh2(v.x, v.y), packh2(v.z, v.w));
        } else if constexpr (EPI == EPI_FC1) {
            __half* out = (__half*)out_v;
            v.x *= normcdff(v.x); v.y *= normcdff(v.y);
            v.z *= normcdff(v.z); v.w *= normcdff(v.w);
            *(uint2*)&out[grow * NDIM + gcol] = make_uint2(packh2(v.x, v.y), packh2(v.z, v.w));
        } else {  // EPI_FC2
            float* out = (float*)out_v;
            const __half* res = (const __half*)res_v;  // xo fp16
            uint2 raw = *(const uint2*)&res[grow * (size_t)CDIM + gcol];
            float2 r0 = __half22float2(*(__half2*)&raw.x);
            float2 r1 = __half22float2(*(__half2*)&raw.y);
            v.x += r0.x; v.y += r0.y; v.z += r1.x; v.w += r1.y;
            *(float4*)&out[grow * (size_t)NDIM + gcol] = v;
        }
    }
}

// ---------------- attention: register-softmax + ldmatrix operand loads ----------------
// Block = (head-pair hp, window). 8 warps: hh = wid>>2 (head), strip = wid&3 (16 rows).
#define AQLD 72
#define ATTN_DYN (3 * 64 * AQLD * 2)   // 27648 B

__global__ __launch_bounds__(256) void attn_kernel(const __half* __restrict__ qkv,
                                                   __half* __restrict__ o)
{
    extern __shared__ char smraw[];
    __half* qs = (__half*)smraw;
    __half* ks = qs + 64 * AQLD;
    __half* vs = ks + 64 * AQLD;

    const int hp  = blockIdx.x;
    const int win = blockIdx.y;
    const int tid = threadIdx.x;
    const int wid = tid >> 5;
    const int lane = tid & 31;

    const __half* base = qkv + (size_t)win * 36864 + hp * 64;
#pragma unroll
    for (int s = 0; s < 2; s++) {
        int idx = tid + s * 256;
        int r = idx >> 3, c8 = idx & 7;
        const __half* rp = base + (size_t)r * 576 + c8 * 8;
        *(uint4*)&qs[r * AQLD + c8 * 8] = *(const uint4*)(rp);
        *(uint4*)&ks[r * AQLD + c8 * 8] = *(const uint4*)(rp + 192);
        *(uint4*)&vs[r * AQLD + c8 * 8] = *(const uint4*)(rp + 384);
    }
    __syncthreads();

    const int hh    = wid >> 2;     // head within pair
    const int strip = wid & 3;      // 16-row strip
    const int gid   = lane >> 2;    // 0..7
    const int tig   = lane & 3;     // 0..3
    const int r0    = strip * 16;
    const int r1    = r0 + gid;     // output rows r1, r1+8
    const int kb    = hh * 32;

    uint32_t qsu = (uint32_t)__cvta_generic_to_shared(qs);
    uint32_t ksu = (uint32_t)__cvta_generic_to_shared(ks);
    uint32_t vsu = (uint32_t)__cvta_generic_to_shared(vs);

    // ldmatrix per-lane address patterns (bytes):
    // A x4: m0 rows0-7@k0, m1 rows8-15@k0, m2 rows0-7@k0+8, m3 rows8-15@k0+8
    const uint32_t a_off  = (uint32_t)(((lane & 15) * AQLD + (lane >> 4) * 8) * 2);
    // K x4 (non-trans): m0 j0-7@k0, m1 j0-7@k0+8, m2 j8-15@k0, m3 j8-15@k0+8
    const uint32_t k_off  = (uint32_t)((((lane & 7) + ((lane >> 4) << 3)) * AQLD
                                        + (((lane >> 3) & 1) << 3)) * 2);
    // V x4 (trans): m0 k0-7@d0, m1 k8-15@d0, m2 k0-7@d0+8, m3 k8-15@d0+8
    const uint32_t v_off  = (uint32_t)((((lane & 7) + (((lane >> 3) & 1) << 3)) * AQLD
                                        + ((lane >> 4) << 3)) * 2);

    // Q A-fragments: 2 k-tiles
    uint32_t aq[2][4];
#pragma unroll
    for (int kt = 0; kt < 2; kt++)
        ldsm4(aq[kt], qsu + (uint32_t)((r0 * AQLD + kb + kt * 16) * 2) + a_off);

    // S = Q K^T : 8 j-tiles (m16n8), K B-frags via ldsm4 (2 j-tiles per load)
    float sc[8][4];
#pragma unroll
    for (int jt = 0; jt < 8; jt++) { sc[jt][0] = sc[jt][1] = sc[jt][2] = sc[jt][3] = 0.f; }
#pragma unroll
    for (int jp = 0; jp < 4; jp++) {
#pragma unroll
        for (int kt = 0; kt < 2; kt++) {
            uint32_t kf[4];
            ldsm4(kf, ksu + (uint32_t)(((jp * 16) * AQLD + kb + kt * 16) * 2) + k_off);
            mma16816(sc[jp * 2],     aq[kt], &kf[0]);
            mma16816(sc[jp * 2 + 1], aq[kt], &kf[2]);
        }
    }

    // register softmax over rows r1 (c0,c1) and r1+8 (c2,c3); reduce across lane quad
    const float scale = 0.17677669529663687f;
    float m1 = -1e30f, m2 = -1e30f;
#pragma unroll
    for (int jt = 0; jt < 8; jt++) {
        sc[jt][0] *= scale; sc[jt][1] *= scale; sc[jt][2] *= scale; sc[jt][3] *= scale;
        m1 = fmaxf(m1, fmaxf(sc[jt][0], sc[jt][1]));
        m2 = fmaxf(m2, fmaxf(sc[jt][2], sc[jt][3]));
    }
    m1 = fmaxf(m1, __shfl_xor_sync(0xffffffffu, m1, 1));
    m1 = fmaxf(m1, __shfl_xor_sync(0xffffffffu, m1, 2));
    m2 = fmaxf(m2, __shfl_xor_sync(0xffffffffu, m2, 1));
    m2 = fmaxf(m2, __shfl_xor_sync(0xffffffffu, m2, 2));
    float s1 = 0.f, s2 = 0.f;
#pragma unroll
    for (int jt = 0; jt < 8; jt++) {
        sc[jt][0] = __expf(sc[jt][0] - m1); sc[jt][1] = __expf(sc[jt][1] - m1);
        sc[jt][2] = __expf(sc[jt][2] - m2); sc[jt][3] = __expf(sc[jt][3] - m2);
        s1 += sc[jt][0] + sc[jt][1];
        s2 += sc[jt][2] + sc[jt][3];
    }
    s1 += __shfl_xor_sync(0xffffffffu, s1, 1);
    s1 += __shfl_xor_sync(0xffffffffu, s1, 2);
    s2 += __shfl_xor_sync(0xffffffffu, s2, 1);
    s2 += __shfl_xor_sync(0xffffffffu, s2, 2);
    float i1 = 1.f / s1, i2 = 1.f / s2;

    // P -> fp16 A-fragment halves
    uint32_t phr1[8], phr2[8];
#pragma unroll
    for (int jt = 0; jt < 8; jt++) {
        phr1[jt] = packh2(sc[jt][0] * i1, sc[jt][1] * i1);
        phr2[jt] = packh2(sc[jt][2] * i2, sc[jt][3] * i2);
    }

    // O = P V : V B-frags via ldsm4t (2 d-tiles per load)
    float oc[4][4];
#pragma unroll
    for (int nt = 0; nt < 4; nt++) { oc[nt][0] = oc[nt][1] = oc[nt][2] = oc[nt][3] = 0.f; }
#pragma unroll
    for (int kt = 0; kt < 4; kt++) {
        uint32_t pa[4] = { phr1[2 * kt], phr2[2 * kt], phr1[2 * kt + 1], phr2[2 * kt + 1] };
#pragma unroll
        for (int dp = 0; dp < 2; dp++) {
            uint32_t vf[4];
            ldsm4t(vf, vsu + (uint32_t)(((kt * 16) * AQLD + kb + dp * 16) * 2) + v_off);
            mma16816(oc[dp * 2],     pa, &vf[0]);
            mma16816(oc[dp * 2 + 1], pa, &vf[2]);
        }
    }

    // write O straight from accumulators (rows r1, r1+8; cols tig*2,+1 per n-tile)
    size_t ro1 = (size_t)(win * 64 + r1) * 192 + hp * 64 + kb;
    size_t ro2 = ro1 + (size_t)8 * 192;
#pragma unroll
    for (int nt = 0; nt < 4; nt++) {
        int dc = nt * 8 + tig * 2;
        *(uint32_t*)&o[ro1 + dc] = packh2(oc[nt][0], oc[nt][1]);
        *(uint32_t*)&o[ro2 + dc] = packh2(oc[nt][2], oc[nt][3]);
    }
}

// ---------------- launch ----------------
extern "C" void kernel_launch(void* const* d_in, const int* in_sizes, int n_in,
                              void* d_out, int out_size)
{
    (void)in_sizes; (void)n_in; (void)out_size;
    const float* x      = (const float*)d_in[0];
    const float* g1     = (const float*)d_in[1];
    const float* b1     = (const float*)d_in[2];
    const float* w_qkv  = (const float*)d_in[3];
    const float* b_qkv  = (const float*)d_in[4];
    const float* w_proj = (const float*)d_in[5];
    const float* b_proj = (const float*)d_in[6];
    const float* g2     = (const float*)d_in[7];
    const float* b2     = (const float*)d_in[8];
    const float* w_fc1  = (const float*)d_in[9];
    const float* b_fc1  = (const float*)d_in[10];
    const float* w_fc2  = (const float*)d_in[11];
    const float* b_fc2  = (const float*)d_in[12];
    float* out = (float*)d_out;

    __half *ln, *big, *ow, *xo, *wqkv_h, *wproj_h, *wfc1_h, *wfc2_h;
    cudaGetSymbolAddress((void**)&ln,  g_ln);
    cudaGetSymbolAddress((void**)&big, g_big);
    cudaGetSymbolAddress((void**)&ow,  g_ow);
    cudaGetSymbolAddress((void**)&xo,  g_xo);
    cudaGetSymbolAddress((void**)&wqkv_h, g_wqkv_h);
    cudaGetSymbolAddress((void**)&wproj_h, g_wproj_h);
    cudaGetSymbolAddress((void**)&wfc1_h, g_wfc1_h);
    cudaGetSymbolAddress((void**)&wfc2_h, g_wfc2_h);

    const int SB = (int)GEMM_DYN;
    cudaFuncSetAttribute(gemm_kernel<192, 576, EPI_QKV>,  cudaFuncAttributeMaxDynamicSharedMemorySize, SB);
    cudaFuncSetAttribute(gemm_kernel<192, 192, EPI_PROJ>, cudaFuncAttributeMaxDynamicSharedMemorySize, SB);
    cudaFuncSetAttribute(gemm_kernel<192, 768, EPI_FC1>,  cudaFuncAttributeMaxDynamicSharedMemorySize, SB);
    cudaFuncSetAttribute(gemm_kernel<768, 192, EPI_FC2>,  cudaFuncAttributeMaxDynamicSharedMemorySize, SB);

    // 0. all weights fp32 -> fp16, one launch
    {
        int n0 = 192 * 576 / 4, n1 = 192 * 192 / 4, n2 = 192 * 768 / 4, n3 = 768 * 192 / 4;
        int total = n0 + n1 + n2 + n3;
        f2h_all_kernel<<<(total + 255) / 256, 256>>>(w_qkv, wqkv_h, n0, w_proj, wproj_h, n1,
                                                     w_fc1, wfc1_h, n2, w_fc2, wfc2_h, n3);
    }

    // 1. LN1 + window partition (fp32 in, fp16 out)
    ln_kernel<true, float><<<TOK / 8, 256>>>(x, g1, b1, ln);
    // 2. QKV GEMM: 6 column blocks of 96 (fp16 out)
    gemm_kernel<192, 576, EPI_QKV><<<dim3(6, TOK / GBM), NTHR, SB>>>(ln, wqkv_h, b_qkv, nullptr, big);
    // 3. attention per (head-pair, window): register softmax + ldmatrix
    attn_kernel<<<dim3(3, 4096), 256, ATTN_DYN>>>(big, ow);
    // 4. proj GEMM + window unpartition + residual x -> xo (fp16)
    gemm_kernel<192, 192, EPI_PROJ><<<dim3(2, TOK / GBM), NTHR, SB>>>(ow, wproj_h, b_proj, x, xo);
    // 5. LN2 (fp16 in, fp16 out)
    ln_kernel<false, __half><<<TOK / 8, 256>>>(xo, g2, b2, ln);
    // 6. FC1 GEMM + exact GELU (fp16 out)
    gemm_kernel<192, 768, EPI_FC1><<<dim3(8, TOK / GBM), NTHR, SB>>>(ln, wfc1_h, b_fc1, nullptr, big);
    // 7. FC2 GEMM + residual xo (fp16) -> out (fp32)
    gemm_kernel<768, 192, EPI_FC2><<<dim3(2, TOK / GBM), NTHR, SB>>>(big, wfc2_h, b_fc2, xo, out);
}

// round 16
// speedup vs baseline: 1.0458x; 1.0161x over previous
#include <cuda_runtime.h>
#include <cuda_fp16.h>
#include <cstdint>

#define TOK    262144          // 4*256*256 tokens
#define CDIM   192

// ---------------- scratch (device globals; no allocation) ----------------
__device__ __half g_ln  [(size_t)TOK * 192];   // LN1 (window layout) then LN2 (token layout)
__device__ __half g_big [(size_t)TOK * 768];   // qkv (576 wide) then fc1 activation (768 wide)
__device__ __half g_ow  [(size_t)TOK * 192];   // attention output, window layout
__device__ __half g_xo  [(size_t)TOK * 192];   // post-attention residual, token layout (fp16)
__device__ __half g_wqkv_h[192 * 576];
__device__ __half g_wproj_h[192 * 192];
__device__ __half g_wfc1_h[192 * 768];
__device__ __half g_wfc2_h[768 * 192];

// ---------------- cp.async helpers ----------------
__device__ __forceinline__ void cp_async16(void* smem_dst, const void* gmem_src) {
    uint32_t s = (uint32_t)__cvta_generic_to_shared(smem_dst);
    asm volatile("cp.async.cg.shared.global [%0], [%1], 16;\n" :: "r"(s), "l"(gmem_src));
}
__device__ __forceinline__ void cp_commit() {
    asm volatile("cp.async.commit_group;\n" ::: "memory");
}
template<int N>
__device__ __forceinline__ void cp_wait() {
    asm volatile("cp.async.wait_group %0;\n" :: "n"(N) : "memory");
}

// ---------------- mma.sync / ldmatrix helpers ----------------
__device__ __forceinline__ void mma16816(float* c, const uint32_t* a, const uint32_t* b) {
    asm volatile("mma.sync.aligned.m16n8k16.row.col.f32.f16.f16.f32 "
                 "{%0,%1,%2,%3}, {%4,%5,%6,%7}, {%8,%9}, {%0,%1,%2,%3};"
                 : "+f"(c[0]), "+f"(c[1]), "+f"(c[2]), "+f"(c[3])
                 : "r"(a[0]), "r"(a[1]), "r"(a[2]), "r"(a[3]), "r"(b[0]), "r"(b[1]));
}
__device__ __forceinline__ void ldsm4(uint32_t* d, uint32_t addr) {
    asm volatile("ldmatrix.sync.aligned.m8n8.x4.shared.b16 {%0,%1,%2,%3}, [%4];"
                 : "=r"(d[0]), "=r"(d[1]), "=r"(d[2]), "=r"(d[3]) : "r"(addr));
}
__device__ __forceinline__ void ldsm4t(uint32_t* d, uint32_t addr) {
    asm volatile("ldmatrix.sync.aligned.m8n8.x4.trans.shared.b16 {%0,%1,%2,%3}, [%4];"
                 : "=r"(d[0]), "=r"(d[1]), "=r"(d[2]), "=r"(d[3]) : "r"(addr));
}
__device__ __forceinline__ uint32_t packh2(float lo, float hi) {
    __half2 h = __floats2half2_rn(lo, hi);
    return *(uint32_t*)&h;
}

// ---------------- fused fp32 -> fp16 conversion of all four weights ----------------
__global__ __launch_bounds__(256) void f2h_all_kernel(const float* __restrict__ w0, __half* o0, int n0,
                                                      const float* __restrict__ w1, __half* o1, int n1,
                                                      const float* __restrict__ w2, __half* o2, int n2,
                                                      const float* __restrict__ w3, __half* o3, int n3)
{
    int i = blockIdx.x * 256 + threadIdx.x;
    const float* src; __half* dst;
    if (i < n0)                    { src = w0; dst = o0; }
    else if ((i -= n0) < n1)       { src = w1; dst = o1; }
    else if ((i -= n1) < n2)       { src = w2; dst = o2; }
    else if ((i -= n2) < n3)       { src = w3; dst = o3; }
    else return;
    float4 v = *(const float4*)(src + (size_t)i * 4);
    *(uint2*)(dst + (size_t)i * 4) = make_uint2(packh2(v.x, v.y), packh2(v.z, v.w));
}

// ---------------- LayerNorm (one warp per token), templated input, fp16 output ----------------
template<bool WINDOW_DST, typename T>
__global__ __launch_bounds__(256) void ln_kernel(const T* __restrict__ x,
                                                 const float* __restrict__ g,
                                                 const float* __restrict__ b,
                                                 __half* __restrict__ out)
{
    int tok  = blockIdx.x * (blockDim.x >> 5) + (threadIdx.x >> 5);
    int lane = threadIdx.x & 31;
    const T* row = x + (size_t)tok * CDIM;
    float v[6];
    float s = 0.f, s2 = 0.f;
#pragma unroll
    for (int k = 0; k < 6; k++) {
        v[k] = (float)row[lane + 32 * k];
        s  += v[k];
        s2 += v[k] * v[k];
    }
#pragma unroll
    for (int o = 16; o > 0; o >>= 1) {
        s  += __shfl_xor_sync(0xffffffffu, s,  o);
        s2 += __shfl_xor_sync(0xffffffffu, s2, o);
    }
    float mean = s * (1.f / 192.f);
    float var  = s2 * (1.f / 192.f) - mean * mean;
    float inv  = rsqrtf(var + 1e-5f);

    size_t drow;
    if (WINDOW_DST) {
        int bb  = tok >> 16;
        int rem = tok & 65535;
        int h   = rem >> 8;
        int w   = rem & 255;
        int win = (bb << 10) + ((h >> 3) << 5) + (w >> 3);
        int n   = ((h & 7) << 3) + (w & 7);
        drow = (size_t)win * 64 + n;
    } else {
        drow = (size_t)tok;
    }
    __half* orow = out + drow * CDIM;
#pragma unroll
    for (int k = 0; k < 6; k++) {
        int c = lane + 32 * k;
        orow[c] = __float2half_rn((v[k] - mean) * inv * g[c] + b[c]);
    }
}

// ---------------- GEMM: mma.sync + ldmatrix mainloop, smem-staged epilogue ----------------
// 128x96 tile, 256 thr (warp grid 4x2, warp tile 32x48), 3-stage, 2 CTAs/SM.
#define GBM 128
#define GBN 96
#define GBK 64
#define NTHR 256

#define ALDH 72                   // 64 + 8 halves pad (144 B rows; ldsm banks 4i: conflict-free)
#define BLDH 104                  // 96 + 8 halves pad (208 B rows)
#define SA_HALF (GBM * ALDH)      // 9216 halves
#define SB_HALF (GBK * BLDH)      // 6656 halves
#define STAGE_HALF (SA_HALF + SB_HALF)
#define GEMM_DYN (3 * STAGE_HALF * 2)   // 95232 B; epilogue csm 128*100*4 = 51200 fits
#define CLD 100

enum { EPI_QKV = 0, EPI_PROJ = 1, EPI_FC1 = 2, EPI_FC2 = 3 };

// A: [M][KDIM] half row-major; B: [KDIM][NDIM] half row-major.
// EPI_PROJ: res = x (fp32), out = xo (fp16, token scatter).
// EPI_FC2:  res = xo (fp16), out = final (fp32).
template<int KDIM, int NDIM, int EPI>
__global__ __launch_bounds__(NTHR, 2) void gemm_kernel(const __half* __restrict__ A,
                                                       const __half* __restrict__ B,
                                                       const float* __restrict__ bias,
                                                       const void* __restrict__ res_v,
                                                       void* __restrict__ out_v)
{
    extern __shared__ char dynsm[];
    __half* sbase = (__half*)dynsm;
    float*  csm   = (float*)dynsm;

    const int bn   = blockIdx.x;
    const int bm   = blockIdx.y;
    const int tid  = threadIdx.x;
    const int warp = tid >> 5;
    const int lane = tid & 31;
    const int wr   = warp >> 1;   // 0..3 : 32-row group
    const int wc   = warp & 1;    // 0..1 : 48-col group
    const int gid  = lane >> 2;   // 0..7
    const int tig  = lane & 3;    // 0..3

    const __half* Abase = A + (size_t)(bm * GBM) * KDIM;
    const __half* Bbase = B + (size_t)bn * GBN;

    // ldmatrix per-lane address offsets (bytes)
    const uint32_t a_off = (uint32_t)(((lane & 15) * ALDH + (lane >> 4) * 8) * 2);
    const uint32_t b_off = (uint32_t)(((lane & 15) * BLDH + (lane >> 4) * 8) * 2);

    float acc[2][6][4];
#pragma unroll
    for (int i = 0; i < 2; i++)
#pragma unroll
        for (int j = 0; j < 6; j++)
#pragma unroll
            for (int q = 0; q < 4; q++) acc[i][j][q] = 0.f;

    auto issue_stage = [&](int st, int k0) {
        __half* sa = sbase + st * STAGE_HALF;
        __half* sb = sa + SA_HALF;
#pragma unroll
        for (int s = 0; s < 4; s++) {
            int line = tid + s * NTHR;
            int r = line >> 3, c8 = line & 7;
            cp_async16(&sa[r * ALDH + c8 * 8],
                       Abase + (size_t)r * KDIM + k0 + c8 * 8);
        }
#pragma unroll
        for (int s = 0; s < 3; s++) {
            int line = tid + s * NTHR;
            int r = line / 12, c8 = line % 12;
            cp_async16(&sb[r * BLDH + c8 * 8],
                       Bbase + (size_t)(k0 + r) * NDIM + c8 * 8);
        }
        cp_commit();
    };

    constexpr int NK = KDIM / GBK;
    issue_stage(0, 0);
    if (NK > 1) issue_stage(1, GBK);

    // Single-barrier mainloop: wait(cur) -> barrier -> issue(kt+2) -> compute(kt).
#pragma unroll 1
    for (int kt = 0; kt < NK; kt++) {
        if (kt + 1 < NK) cp_wait<1>(); else cp_wait<0>();
        __syncthreads();
        if (kt + 2 < NK) issue_stage((kt + 2) % 3, (kt + 2) * GBK);

        const __half* sa = sbase + (kt % 3) * STAGE_HALF;
        const __half* sb = sa + SA_HALF;
        uint32_t sa_u = (uint32_t)__cvta_generic_to_shared(sa);
        uint32_t sb_u = (uint32_t)__cvta_generic_to_shared(sb);

#pragma unroll
        for (int kk = 0; kk < GBK; kk += 16) {
            uint32_t af[2][4];
#pragma unroll
            for (int i = 0; i < 2; i++)
                ldsm4(af[i], sa_u + (uint32_t)(((wr * 32 + i * 16) * ALDH + kk) * 2) + a_off);
            uint32_t bf[3][4];
#pragma unroll
            for (int jj = 0; jj < 3; jj++)
                ldsm4t(bf[jj], sb_u + (uint32_t)((kk * BLDH + wc * 48 + jj * 16) * 2) + b_off);
#pragma unroll
            for (int i = 0; i < 2; i++)
#pragma unroll
                for (int j = 0; j < 6; j++)
                    mma16816(acc[i][j], af[i], &bf[j >> 1][(j & 1) * 2]);
        }
    }
    __syncthreads();   // all compute done before csm overwrites stage buffers

    // accumulators -> smem C tile (fp32). C-frag mapping: rows wr*32+i*16+gid(+8),
    // cols wc*48 + j*8 + tig*2 (+1). float2 stores, banks (4*gid+2*tig): conflict-free.
#pragma unroll
    for (int i = 0; i < 2; i++) {
        int rbase = wr * 32 + i * 16 + gid;
#pragma unroll
        for (int j = 0; j < 6; j++) {
            int c = wc * 48 + j * 8 + tig * 2;
            *(float2*)&csm[rbase * CLD + c]       = make_float2(acc[i][j][0], acc[i][j][1]);
            *(float2*)&csm[(rbase + 8) * CLD + c] = make_float2(acc[i][j][2], acc[i][j][3]);
        }
    }
    __syncthreads();

    // epilogue: 128x96 = 3072 float4-groups, 12 per thread, fully coalesced
#pragma unroll
    for (int e = tid; e < GBM * (GBN / 4); e += NTHR) {
        int r  = e / 24;
        int c4 = e % 24;
        int gcol = bn * GBN + c4 * 4;
        size_t grow = (size_t)bm * GBM + r;
        float4 v  = *(float4*)&csm[r * CLD + c4 * 4];
        float4 bb = *(const float4*)&bias[gcol];
        v.x += bb.x; v.y += bb.y; v.z += bb.z; v.w += bb.w;

        if constexpr (EPI == EPI_QKV) {
            __half* out = (__half*)out_v;
            *(uint2*)&out[grow * NDIM + gcol] = make_uint2(packh2(v.x, v.y), packh2(v.z, v.w));
        } else if constexpr (EPI == EPI_PROJ) {
            __half* out = (__half*)out_v;              // xo fp16
            const float* res = (const float*)res_v;    // original x fp32
            int rg  = (int)grow;
            int win = rg >> 6, n = rg & 63;
            int bbi = win >> 10, wrw = win & 1023;
            int h   = ((wrw >> 5) << 3) + (n >> 3);
            int w   = ((wrw & 31) << 3) + (n & 7);
            size_t t = ((size_t)bbi << 16) + ((size_t)h << 8) + (size_t)w;
            float4 rr = *(const float4*)&res[t * CDIM + gcol];
            v.x += rr.x; v.y += rr.y; v.z += rr.z; v.w += rr.w;
            *(uint2*)&out[t * CDIM + gcol] = make_uint2(packh2(v.x, v.y), packh2(v.z, v.w));
        } else if constexpr (EPI == EPI_FC1) {
            __half* out = (__half*)out_v;
            v.x *= normcdff(v.x); v.y *= normcdff(v.y);
            v.z *= normcdff(v.z); v.w *= normcdff(v.w);
            *(uint2*)&out[grow * NDIM + gcol] = make_uint2(packh2(v.x, v.y), packh2(v.z, v.w));
        } else {  // EPI_FC2
            float* out = (float*)out_v;
            const __half* res = (const __half*)res_v;  // xo fp16
            uint2 raw = *(const uint2*)&res[grow * (size_t)CDIM + gcol];
            float2 r0 = __half22float2(*(__half2*)&raw.x);
            float2 r1 = __half22float2(*(__half2*)&raw.y);
            v.x += r0.x; v.y += r0.y; v.z += r1.x; v.w += r1.y;
            *(float4*)&out[grow * (size_t)NDIM + gcol] = v;
        }
    }
}

// ---------------- attention: register-softmax + ldmatrix operand loads (R15) ----------------
#define AQLD 72
#define ATTN_DYN (3 * 64 * AQLD * 2)   // 27648 B

__global__ __launch_bounds__(256) void attn_kernel(const __half* __restrict__ qkv,
                                                   __half* __restrict__ o)
{
    extern __shared__ char smraw[];
    __half* qs = (__half*)smraw;
    __half* ks = qs + 64 * AQLD;
    __half* vs = ks + 64 * AQLD;

    const int hp  = blockIdx.x;
    const int win = blockIdx.y;
    const int tid = threadIdx.x;
    const int wid = tid >> 5;
    const int lane = tid & 31;

    const __half* base = qkv + (size_t)win * 36864 + hp * 64;
#pragma unroll
    for (int s = 0; s < 2; s++) {
        int idx = tid + s * 256;
        int r = idx >> 3, c8 = idx & 7;
        const __half* rp = base + (size_t)r * 576 + c8 * 8;
        *(uint4*)&qs[r * AQLD + c8 * 8] = *(const uint4*)(rp);
        *(uint4*)&ks[r * AQLD + c8 * 8] = *(const uint4*)(rp + 192);
        *(uint4*)&vs[r * AQLD + c8 * 8] = *(const uint4*)(rp + 384);
    }
    __syncthreads();

    const int hh    = wid >> 2;
    const int strip = wid & 3;
    const int gid   = lane >> 2;
    const int tig   = lane & 3;
    const int r0    = strip * 16;
    const int r1    = r0 + gid;
    const int kb    = hh * 32;

    uint32_t qsu = (uint32_t)__cvta_generic_to_shared(qs);
    uint32_t ksu = (uint32_t)__cvta_generic_to_shared(ks);
    uint32_t vsu = (uint32_t)__cvta_generic_to_shared(vs);

    const uint32_t a_off  = (uint32_t)(((lane & 15) * AQLD + (lane >> 4) * 8) * 2);
    const uint32_t k_off  = (uint32_t)((((lane & 7) + ((lane >> 4) << 3)) * AQLD
                                        + (((lane >> 3) & 1) << 3)) * 2);
    const uint32_t v_off  = (uint32_t)((((lane & 7) + (((lane >> 3) & 1) << 3)) * AQLD
                                        + ((lane >> 4) << 3)) * 2);

    uint32_t aq[2][4];
#pragma unroll
    for (int kt = 0; kt < 2; kt++)
        ldsm4(aq[kt], qsu + (uint32_t)((r0 * AQLD + kb + kt * 16) * 2) + a_off);

    float sc[8][4];
#pragma unroll
    for (int jt = 0; jt < 8; jt++) { sc[jt][0] = sc[jt][1] = sc[jt][2] = sc[jt][3] = 0.f; }
#pragma unroll
    for (int jp = 0; jp < 4; jp++) {
#pragma unroll
        for (int kt = 0; kt < 2; kt++) {
            uint32_t kf[4];
            ldsm4(kf, ksu + (uint32_t)(((jp * 16) * AQLD + kb + kt * 16) * 2) + k_off);
            mma16816(sc[jp * 2],     aq[kt], &kf[0]);
            mma16816(sc[jp * 2 + 1], aq[kt], &kf[2]);
        }
    }

    const float scale = 0.17677669529663687f;
    float m1 = -1e30f, m2 = -1e30f;
#pragma unroll
    for (int jt = 0; jt < 8; jt++) {
        sc[jt][0] *= scale; sc[jt][1] *= scale; sc[jt][2] *= scale; sc[jt][3] *= scale;
        m1 = fmaxf(m1, fmaxf(sc[jt][0], sc[jt][1]));
        m2 = fmaxf(m2, fmaxf(sc[jt][2], sc[jt][3]));
    }
    m1 = fmaxf(m1, __shfl_xor_sync(0xffffffffu, m1, 1));
    m1 = fmaxf(m1, __shfl_xor_sync(0xffffffffu, m1, 2));
    m2 = fmaxf(m2, __shfl_xor_sync(0xffffffffu, m2, 1));
    m2 = fmaxf(m2, __shfl_xor_sync(0xffffffffu, m2, 2));
    float s1 = 0.f, s2 = 0.f;
#pragma unroll
    for (int jt = 0; jt < 8; jt++) {
        sc[jt][0] = __expf(sc[jt][0] - m1); sc[jt][1] = __expf(sc[jt][1] - m1);
        sc[jt][2] = __expf(sc[jt][2] - m2); sc[jt][3] = __expf(sc[jt][3] - m2);
        s1 += sc[jt][0] + sc[jt][1];
        s2 += sc[jt][2] + sc[jt][3];
    }
    s1 += __shfl_xor_sync(0xffffffffu, s1, 1);
    s1 += __shfl_xor_sync(0xffffffffu, s1, 2);
    s2 += __shfl_xor_sync(0xffffffffu, s2, 1);
    s2 += __shfl_xor_sync(0xffffffffu, s2, 2);
    float i1 = 1.f / s1, i2 = 1.f / s2;

    uint32_t phr1[8], phr2[8];
#pragma unroll
    for (int jt = 0; jt < 8; jt++) {
        phr1[jt] = packh2(sc[jt][0] * i1, sc[jt][1] * i1);
        phr2[jt] = packh2(sc[jt][2] * i2, sc[jt][3] * i2);
    }

    float oc[4][4];
#pragma unroll
    for (int nt = 0; nt < 4; nt++) { oc[nt][0] = oc[nt][1] = oc[nt][2] = oc[nt][3] = 0.f; }
#pragma unroll
    for (int kt = 0; kt < 4; kt++) {
        uint32_t pa[4] = { phr1[2 * kt], phr2[2 * kt], phr1[2 * kt + 1], phr2[2 * kt + 1] };
#pragma unroll
        for (int dp = 0; dp < 2; dp++) {
            uint32_t vf[4];
            ldsm4t(vf, vsu + (uint32_t)(((kt * 16) * AQLD + kb + dp * 16) * 2) + v_off);
            mma16816(oc[dp * 2],     pa, &vf[0]);
            mma16816(oc[dp * 2 + 1], pa, &vf[2]);
        }
    }

    size_t ro1 = (size_t)(win * 64 + r1) * 192 + hp * 64 + kb;
    size_t ro2 = ro1 + (size_t)8 * 192;
#pragma unroll
    for (int nt = 0; nt < 4; nt++) {
        int dc = nt * 8 + tig * 2;
        *(uint32_t*)&o[ro1 + dc] = packh2(oc[nt][0], oc[nt][1]);
        *(uint32_t*)&o[ro2 + dc] = packh2(oc[nt][2], oc[nt][3]);
    }
}

// ---------------- launch ----------------
extern "C" void kernel_launch(void* const* d_in, const int* in_sizes, int n_in,
                              void* d_out, int out_size)
{
    (void)in_sizes; (void)n_in; (void)out_size;
    const float* x      = (const float*)d_in[0];
    const float* g1     = (const float*)d_in[1];
    const float* b1     = (const float*)d_in[2];
    const float* w_qkv  = (const float*)d_in[3];
    const float* b_qkv  = (const float*)d_in[4];
    const float* w_proj = (const float*)d_in[5];
    const float* b_proj = (const float*)d_in[6];
    const float* g2     = (const float*)d_in[7];
    const float* b2     = (const float*)d_in[8];
    const float* w_fc1  = (const float*)d_in[9];
    const float* b_fc1  = (const float*)d_in[10];
    const float* w_fc2  = (const float*)d_in[11];
    const float* b_fc2  = (const float*)d_in[12];
    float* out = (float*)d_out;

    __half *ln, *big, *ow, *xo, *wqkv_h, *wproj_h, *wfc1_h, *wfc2_h;
    cudaGetSymbolAddress((void**)&ln,  g_ln);
    cudaGetSymbolAddress((void**)&big, g_big);
    cudaGetSymbolAddress((void**)&ow,  g_ow);
    cudaGetSymbolAddress((void**)&xo,  g_xo);
    cudaGetSymbolAddress((void**)&wqkv_h, g_wqkv_h);
    cudaGetSymbolAddress((void**)&wproj_h, g_wproj_h);
    cudaGetSymbolAddress((void**)&wfc1_h, g_wfc1_h);
    cudaGetSymbolAddress((void**)&wfc2_h, g_wfc2_h);

    const int SB = (int)GEMM_DYN;
    cudaFuncSetAttribute(gemm_kernel<192, 576, EPI_QKV>,  cudaFuncAttributeMaxDynamicSharedMemorySize, SB);
    cudaFuncSetAttribute(gemm_kernel<192, 192, EPI_PROJ>, cudaFuncAttributeMaxDynamicSharedMemorySize, SB);
    cudaFuncSetAttribute(gemm_kernel<192, 768, EPI_FC1>,  cudaFuncAttributeMaxDynamicSharedMemorySize, SB);
    cudaFuncSetAttribute(gemm_kernel<768, 192, EPI_FC2>,  cudaFuncAttributeMaxDynamicSharedMemorySize, SB);

    // 0. all weights fp32 -> fp16, one launch
    {
        int n0 = 192 * 576 / 4, n1 = 192 * 192 / 4, n2 = 192 * 768 / 4, n3 = 768 * 192 / 4;
        int total = n0 + n1 + n2 + n3;
        f2h_all_kernel<<<(total + 255) / 256, 256>>>(w_qkv, wqkv_h, n0, w_proj, wproj_h, n1,
                                                     w_fc1, wfc1_h, n2, w_fc2, wfc2_h, n3);
    }

    // 1. LN1 + window partition (fp32 in, fp16 out)
    ln_kernel<true, float><<<TOK / 8, 256>>>(x, g1, b1, ln);
    // 2. QKV GEMM: 6 column blocks of 96 (fp16 out)
    gemm_kernel<192, 576, EPI_QKV><<<dim3(6, TOK / GBM), NTHR, SB>>>(ln, wqkv_h, b_qkv, nullptr, big);
    // 3. attention per (head-pair, window): register softmax + ldmatrix
    attn_kernel<<<dim3(3, 4096), 256, ATTN_DYN>>>(big, ow);
    // 4. proj GEMM + window unpartition + residual x -> xo (fp16)
    gemm_kernel<192, 192, EPI_PROJ><<<dim3(2, TOK / GBM), NTHR, SB>>>(ow, wproj_h, b_proj, x, xo);
    // 5. LN2 (fp16 in, fp16 out)
    ln_kernel<false, __half><<<TOK / 8, 256>>>(xo, g2, b2, ln);
    // 6. FC1 GEMM + exact GELU (fp16 out)
    gemm_kernel<192, 768, EPI_FC1><<<dim3(8, TOK / GBM), NTHR, SB>>>(ln, wfc1_h, b_fc1, nullptr, big);
    // 7. FC2 GEMM + residual xo (fp16) -> out (fp32)
    gemm_kernel<768, 192, EPI_FC2><<<dim3(2, TOK / GBM), NTHR, SB>>>(big, wfc2_h, b_fc2, xo, out);
}

// round 17
// speedup vs baseline: 1.0469x; 1.0011x over previous
#include <cuda_runtime.h>
#include <cuda_fp16.h>
#include <cstdint>

#define TOK    262144          // 4*256*256 tokens
#define CDIM   192

// ---------------- scratch (device globals; no allocation) ----------------
__device__ __half g_ln  [(size_t)TOK * 192];   // LN1 (window layout) then LN2 (token layout)
__device__ __half g_big [(size_t)TOK * 768];   // qkv (576 wide) then fc1 activation (768 wide)
__device__ __half g_ow  [(size_t)TOK * 192];   // attention output, window layout
__device__ __half g_xo  [(size_t)TOK * 192];   // post-attention residual, token layout (fp16)
__device__ __half g_wqkv_h[192 * 576];
__device__ __half g_wproj_h[192 * 192];
__device__ __half g_wfc1_h[192 * 768];
__device__ __half g_wfc2_h[768 * 192];

// ---------------- cp.async helpers ----------------
__device__ __forceinline__ void cp_async16(void* smem_dst, const void* gmem_src) {
    uint32_t s = (uint32_t)__cvta_generic_to_shared(smem_dst);
    asm volatile("cp.async.cg.shared.global [%0], [%1], 16;\n" :: "r"(s), "l"(gmem_src));
}
__device__ __forceinline__ void cp_commit() {
    asm volatile("cp.async.commit_group;\n" ::: "memory");
}
template<int N>
__device__ __forceinline__ void cp_wait() {
    asm volatile("cp.async.wait_group %0;\n" :: "n"(N) : "memory");
}

// ---------------- mma.sync / ldmatrix helpers ----------------
__device__ __forceinline__ void mma16816(float* c, const uint32_t* a, const uint32_t* b) {
    asm volatile("mma.sync.aligned.m16n8k16.row.col.f32.f16.f16.f32 "
                 "{%0,%1,%2,%3}, {%4,%5,%6,%7}, {%8,%9}, {%0,%1,%2,%3};"
                 : "+f"(c[0]), "+f"(c[1]), "+f"(c[2]), "+f"(c[3])
                 : "r"(a[0]), "r"(a[1]), "r"(a[2]), "r"(a[3]), "r"(b[0]), "r"(b[1]));
}
__device__ __forceinline__ void ldsm4(uint32_t* d, uint32_t addr) {
    asm volatile("ldmatrix.sync.aligned.m8n8.x4.shared.b16 {%0,%1,%2,%3}, [%4];"
                 : "=r"(d[0]), "=r"(d[1]), "=r"(d[2]), "=r"(d[3]) : "r"(addr));
}
__device__ __forceinline__ void ldsm4t(uint32_t* d, uint32_t addr) {
    asm volatile("ldmatrix.sync.aligned.m8n8.x4.trans.shared.b16 {%0,%1,%2,%3}, [%4];"
                 : "=r"(d[0]), "=r"(d[1]), "=r"(d[2]), "=r"(d[3]) : "r"(addr));
}
__device__ __forceinline__ uint32_t packh2(float lo, float hi) {
    __half2 h = __floats2half2_rn(lo, hi);
    return *(uint32_t*)&h;
}

// ---------------- fused fp32 -> fp16 conversion of all four weights ----------------
__global__ __launch_bounds__(256) void f2h_all_kernel(const float* __restrict__ w0, __half* o0, int n0,
                                                      const float* __restrict__ w1, __half* o1, int n1,
                                                      const float* __restrict__ w2, __half* o2, int n2,
                                                      const float* __restrict__ w3, __half* o3, int n3)
{
    int i = blockIdx.x * 256 + threadIdx.x;
    const float* src; __half* dst;
    if (i < n0)                    { src = w0; dst = o0; }
    else if ((i -= n0) < n1)       { src = w1; dst = o1; }
    else if ((i -= n1) < n2)       { src = w2; dst = o2; }
    else if ((i -= n2) < n3)       { src = w3; dst = o3; }
    else return;
    float4 v = *(const float4*)(src + (size_t)i * 4);
    *(uint2*)(dst + (size_t)i * 4) = make_uint2(packh2(v.x, v.y), packh2(v.z, v.w));
}

// ---------------- LayerNorm (one warp per token), templated input, fp16 output ----------------
template<bool WINDOW_DST, typename T>
__global__ __launch_bounds__(256) void ln_kernel(const T* __restrict__ x,
                                                 const float* __restrict__ g,
                                                 const float* __restrict__ b,
                                                 __half* __restrict__ out)
{
    int tok  = blockIdx.x * (blockDim.x >> 5) + (threadIdx.x >> 5);
    int lane = threadIdx.x & 31;
    const T* row = x + (size_t)tok * CDIM;
    float v[6];
    float s = 0.f, s2 = 0.f;
#pragma unroll
    for (int k = 0; k < 6; k++) {
        v[k] = (float)row[lane + 32 * k];
        s  += v[k];
        s2 += v[k] * v[k];
    }
#pragma unroll
    for (int o = 16; o > 0; o >>= 1) {
        s  += __shfl_xor_sync(0xffffffffu, s,  o);
        s2 += __shfl_xor_sync(0xffffffffu, s2, o);
    }
    float mean = s * (1.f / 192.f);
    float var  = s2 * (1.f / 192.f) - mean * mean;
    float inv  = rsqrtf(var + 1e-5f);

    size_t drow;
    if (WINDOW_DST) {
        int bb  = tok >> 16;
        int rem = tok & 65535;
        int h   = rem >> 8;
        int w   = rem & 255;
        int win = (bb << 10) + ((h >> 3) << 5) + (w >> 3);
        int n   = ((h & 7) << 3) + (w & 7);
        drow = (size_t)win * 64 + n;
    } else {
        drow = (size_t)tok;
    }
    __half* orow = out + drow * CDIM;
#pragma unroll
    for (int k = 0; k < 6; k++) {
        int c = lane + 32 * k;
        orow[c] = __float2half_rn((v[k] - mean) * inv * g[c] + b[c]);
    }
}

// ---------------- GEMM: mma.sync + ldmatrix, 128x96 tile, 2-stage, 3 CTAs/SM ----------------
#define GBM 128
#define GBN 96
#define GBK 64
#define NTHR 256

#define ALDH 72                   // 64 + 8 halves pad (144 B rows; ldsm banks 4i: conflict-free)
#define BLDH 104                  // 96 + 8 halves pad (208 B rows)
#define SA_HALF (GBM * ALDH)      // 9216 halves
#define SB_HALF (GBK * BLDH)      // 6656 halves
#define STAGE_HALF (SA_HALF + SB_HALF)
#define GEMM_DYN (2 * STAGE_HALF * 2)   // 63488 B; 3 CTAs/SM = 190 KB. csm 51200 fits.
#define CLD 100

enum { EPI_QKV = 0, EPI_PROJ = 1, EPI_FC1 = 2, EPI_FC2 = 3 };

// A: [M][KDIM] half row-major; B: [KDIM][NDIM] half row-major.
// EPI_PROJ: res = x (fp32), out = xo (fp16, token scatter).
// EPI_FC2:  res = xo (fp16), out = final (fp32).
template<int KDIM, int NDIM, int EPI>
__global__ __launch_bounds__(NTHR, 3) void gemm_kernel(const __half* __restrict__ A,
                                                       const __half* __restrict__ B,
                                                       const float* __restrict__ bias,
                                                       const void* __restrict__ res_v,
                                                       void* __restrict__ out_v)
{
    extern __shared__ char dynsm[];
    __half* sbase = (__half*)dynsm;
    float*  csm   = (float*)dynsm;

    const int bn   = blockIdx.x;
    const int bm   = blockIdx.y;
    const int tid  = threadIdx.x;
    const int warp = tid >> 5;
    const int lane = tid & 31;
    const int wr   = warp >> 1;   // 0..3 : 32-row group
    const int wc   = warp & 1;    // 0..1 : 48-col group
    const int gid  = lane >> 2;   // 0..7
    const int tig  = lane & 3;    // 0..3

    const __half* Abase = A + (size_t)(bm * GBM) * KDIM;
    const __half* Bbase = B + (size_t)bn * GBN;

    const uint32_t a_off = (uint32_t)(((lane & 15) * ALDH + (lane >> 4) * 8) * 2);
    const uint32_t b_off = (uint32_t)(((lane & 15) * BLDH + (lane >> 4) * 8) * 2);

    float acc[2][6][4];
#pragma unroll
    for (int i = 0; i < 2; i++)
#pragma unroll
        for (int j = 0; j < 6; j++)
#pragma unroll
            for (int q = 0; q < 4; q++) acc[i][j][q] = 0.f;

    auto issue_stage = [&](int st, int k0) {
        __half* sa = sbase + st * STAGE_HALF;
        __half* sb = sa + SA_HALF;
#pragma unroll
        for (int s = 0; s < 4; s++) {
            int line = tid + s * NTHR;
            int r = line >> 3, c8 = line & 7;
            cp_async16(&sa[r * ALDH + c8 * 8],
                       Abase + (size_t)r * KDIM + k0 + c8 * 8);
        }
#pragma unroll
        for (int s = 0; s < 3; s++) {
            int line = tid + s * NTHR;
            int r = line / 12, c8 = line % 12;
            cp_async16(&sb[r * BLDH + c8 * 8],
                       Bbase + (size_t)(k0 + r) * NDIM + c8 * 8);
        }
        cp_commit();
    };

    constexpr int NK = KDIM / GBK;
    issue_stage(0, 0);

    // 2-stage mainloop: wait(stage kt) -> barrier -> issue(kt+1) -> compute(kt).
    // The barrier retires compute(kt-1), which used the buffer issue overwrites.
#pragma unroll 1
    for (int kt = 0; kt < NK; kt++) {
        cp_wait<0>();
        __syncthreads();
        if (kt + 1 < NK) issue_stage((kt + 1) & 1, (kt + 1) * GBK);

        const __half* sa = sbase + (kt & 1) * STAGE_HALF;
        const __half* sb = sa + SA_HALF;
        uint32_t sa_u = (uint32_t)__cvta_generic_to_shared(sa);
        uint32_t sb_u = (uint32_t)__cvta_generic_to_shared(sb);

#pragma unroll
        for (int kk = 0; kk < GBK; kk += 16) {
            uint32_t af[2][4];
#pragma unroll
            for (int i = 0; i < 2; i++)
                ldsm4(af[i], sa_u + (uint32_t)(((wr * 32 + i * 16) * ALDH + kk) * 2) + a_off);
            uint32_t bf[3][4];
#pragma unroll
            for (int jj = 0; jj < 3; jj++)
                ldsm4t(bf[jj], sb_u + (uint32_t)((kk * BLDH + wc * 48 + jj * 16) * 2) + b_off);
#pragma unroll
            for (int i = 0; i < 2; i++)
#pragma unroll
                for (int j = 0; j < 6; j++)
                    mma16816(acc[i][j], af[i], &bf[j >> 1][(j & 1) * 2]);
        }
    }
    __syncthreads();   // all compute done before csm overwrites stage buffers

    // accumulators -> smem C tile (fp32); float2 stores, banks (4*gid+2*tig): conflict-free.
#pragma unroll
    for (int i = 0; i < 2; i++) {
        int rbase = wr * 32 + i * 16 + gid;
#pragma unroll
        for (int j = 0; j < 6; j++) {
            int c = wc * 48 + j * 8 + tig * 2;
            *(float2*)&csm[rbase * CLD + c]       = make_float2(acc[i][j][0], acc[i][j][1]);
            *(float2*)&csm[(rbase + 8) * CLD + c] = make_float2(acc[i][j][2], acc[i][j][3]);
        }
    }
    __syncthreads();

    // epilogue: 128x96 = 3072 float4-groups, 12 per thread, fully coalesced
#pragma unroll
    for (int e = tid; e < GBM * (GBN / 4); e += NTHR) {
        int r  = e / 24;
        int c4 = e % 24;
        int gcol = bn * GBN + c4 * 4;
        size_t grow = (size_t)bm * GBM + r;
        float4 v  = *(float4*)&csm[r * CLD + c4 * 4];
        float4 bb = *(const float4*)&bias[gcol];
        v.x += bb.x; v.y += bb.y; v.z += bb.z; v.w += bb.w;

        if constexpr (EPI == EPI_QKV) {
            __half* out = (__half*)out_v;
            *(uint2*)&out[grow * NDIM + gcol] = make_uint2(packh2(v.x, v.y), packh2(v.z, v.w));
        } else if constexpr (EPI == EPI_PROJ) {
            __half* out = (__half*)out_v;              // xo fp16
            const float* res = (const float*)res_v;    // original x fp32
            int rg  = (int)grow;
            int win = rg >> 6, n = rg & 63;
            int bbi = win >> 10, wrw = win & 1023;
            int h   = ((wrw >> 5) << 3) + (n >> 3);
            int w   = ((wrw & 31) << 3) + (n & 7);
            size_t t = ((size_t)bbi << 16) + ((size_t)h << 8) + (size_t)w;
            float4 rr = *(const float4*)&res[t * CDIM + gcol];
            v.x += rr.x; v.y += rr.y; v.z += rr.z; v.w += rr.w;
            *(uint2*)&out[t * CDIM + gcol] = make_uint2(packh2(v.x, v.y), packh2(v.z, v.w));
        } else if constexpr (EPI == EPI_FC1) {
            __half* out = (__half*)out_v;
            v.x *= normcdff(v.x); v.y *= normcdff(v.y);
            v.z *= normcdff(v.z); v.w *= normcdff(v.w);
            *(uint2*)&out[grow * NDIM + gcol] = make_uint2(packh2(v.x, v.y), packh2(v.z, v.w));
        } else {  // EPI_FC2
            float* out = (float*)out_v;
            const __half* res = (const __half*)res_v;  // xo fp16
            uint2 raw = *(const uint2*)&res[grow * (size_t)CDIM + gcol];
            float2 r0 = __half22float2(*(__half2*)&raw.x);
            float2 r1 = __half22float2(*(__half2*)&raw.y);
            v.x += r0.x; v.y += r0.y; v.z += r1.x; v.w += r1.y;
            *(float4*)&out[grow * (size_t)NDIM + gcol] = v;
        }
    }
}

// ---------------- attention: register-softmax + ldmatrix operand loads (R15) ----------------
#define AQLD 72
#define ATTN_DYN (3 * 64 * AQLD * 2)   // 27648 B

__global__ __launch_bounds__(256) void attn_kernel(const __half* __restrict__ qkv,
                                                   __half* __restrict__ o)
{
    extern __shared__ char smraw[];
    __half* qs = (__half*)smraw;
    __half* ks = qs + 64 * AQLD;
    __half* vs = ks + 64 * AQLD;

    const int hp  = blockIdx.x;
    const int win = blockIdx.y;
    const int tid = threadIdx.x;
    const int wid = tid >> 5;
    const int lane = tid & 31;

    const __half* base = qkv + (size_t)win * 36864 + hp * 64;
#pragma unroll
    for (int s = 0; s < 2; s++) {
        int idx = tid + s * 256;
        int r = idx >> 3, c8 = idx & 7;
        const __half* rp = base + (size_t)r * 576 + c8 * 8;
        *(uint4*)&qs[r * AQLD + c8 * 8] = *(const uint4*)(rp);
        *(uint4*)&ks[r * AQLD + c8 * 8] = *(const uint4*)(rp + 192);
        *(uint4*)&vs[r * AQLD + c8 * 8] = *(const uint4*)(rp + 384);
    }
    __syncthreads();

    const int hh    = wid >> 2;
    const int strip = wid & 3;
    const int gid   = lane >> 2;
    const int tig   = lane & 3;
    const int r0    = strip * 16;
    const int r1    = r0 + gid;
    const int kb    = hh * 32;

    uint32_t qsu = (uint32_t)__cvta_generic_to_shared(qs);
    uint32_t ksu = (uint32_t)__cvta_generic_to_shared(ks);
    uint32_t vsu = (uint32_t)__cvta_generic_to_shared(vs);

    const uint32_t a_off  = (uint32_t)(((lane & 15) * AQLD + (lane >> 4) * 8) * 2);
    const uint32_t k_off  = (uint32_t)((((lane & 7) + ((lane >> 4) << 3)) * AQLD
                                        + (((lane >> 3) & 1) << 3)) * 2);
    const uint32_t v_off  = (uint32_t)((((lane & 7) + (((lane >> 3) & 1) << 3)) * AQLD
                                        + ((lane >> 4) << 3)) * 2);

    uint32_t aq[2][4];
#pragma unroll
    for (int kt = 0; kt < 2; kt++)
        ldsm4(aq[kt], qsu + (uint32_t)((r0 * AQLD + kb + kt * 16) * 2) + a_off);

    float sc[8][4];
#pragma unroll
    for (int jt = 0; jt < 8; jt++) { sc[jt][0] = sc[jt][1] = sc[jt][2] = sc[jt][3] = 0.f; }
#pragma unroll
    for (int jp = 0; jp < 4; jp++) {
#pragma unroll
        for (int kt = 0; kt < 2; kt++) {
            uint32_t kf[4];
            ldsm4(kf, ksu + (uint32_t)(((jp * 16) * AQLD + kb + kt * 16) * 2) + k_off);
            mma16816(sc[jp * 2],     aq[kt], &kf[0]);
            mma16816(sc[jp * 2 + 1], aq[kt], &kf[2]);
        }
    }

    const float scale = 0.17677669529663687f;
    float m1 = -1e30f, m2 = -1e30f;
#pragma unroll
    for (int jt = 0; jt < 8; jt++) {
        sc[jt][0] *= scale; sc[jt][1] *= scale; sc[jt][2] *= scale; sc[jt][3] *= scale;
        m1 = fmaxf(m1, fmaxf(sc[jt][0], sc[jt][1]));
        m2 = fmaxf(m2, fmaxf(sc[jt][2], sc[jt][3]));
    }
    m1 = fmaxf(m1, __shfl_xor_sync(0xffffffffu, m1, 1));
    m1 = fmaxf(m1, __shfl_xor_sync(0xffffffffu, m1, 2));
    m2 = fmaxf(m2, __shfl_xor_sync(0xffffffffu, m2, 1));
    m2 = fmaxf(m2, __shfl_xor_sync(0xffffffffu, m2, 2));
    float s1 = 0.f, s2 = 0.f;
#pragma unroll
    for (int jt = 0; jt < 8; jt++) {
        sc[jt][0] = __expf(sc[jt][0] - m1); sc[jt][1] = __expf(sc[jt][1] - m1);
        sc[jt][2] = __expf(sc[jt][2] - m2); sc[jt][3] = __expf(sc[jt][3] - m2);
        s1 += sc[jt][0] + sc[jt][1];
        s2 += sc[jt][2] + sc[jt][3];
    }
    s1 += __shfl_xor_sync(0xffffffffu, s1, 1);
    s1 += __shfl_xor_sync(0xffffffffu, s1, 2);
    s2 += __shfl_xor_sync(0xffffffffu, s2, 1);
    s2 += __shfl_xor_sync(0xffffffffu, s2, 2);
    float i1 = 1.f / s1, i2 = 1.f / s2;

    uint32_t phr1[8], phr2[8];
#pragma unroll
    for (int jt = 0; jt < 8; jt++) {
        phr1[jt] = packh2(sc[jt][0] * i1, sc[jt][1] * i1);
        phr2[jt] = packh2(sc[jt][2] * i2, sc[jt][3] * i2);
    }

    float oc[4][4];
#pragma unroll
    for (int nt = 0; nt < 4; nt++) { oc[nt][0] = oc[nt][1] = oc[nt][2] = oc[nt][3] = 0.f; }
#pragma unroll
    for (int kt = 0; kt < 4; kt++) {
        uint32_t pa[4] = { phr1[2 * kt], phr2[2 * kt], phr1[2 * kt + 1], phr2[2 * kt + 1] };
#pragma unroll
        for (int dp = 0; dp < 2; dp++) {
            uint32_t vf[4];
            ldsm4t(vf, vsu + (uint32_t)(((kt * 16) * AQLD + kb + dp * 16) * 2) + v_off);
            mma16816(oc[dp * 2],     pa, &vf[0]);
            mma16816(oc[dp * 2 + 1], pa, &vf[2]);
        }
    }

    size_t ro1 = (size_t)(win * 64 + r1) * 192 + hp * 64 + kb;
    size_t ro2 = ro1 + (size_t)8 * 192;
#pragma unroll
    for (int nt = 0; nt < 4; nt++) {
        int dc = nt * 8 + tig * 2;
        *(uint32_t*)&o[ro1 + dc] = packh2(oc[nt][0], oc[nt][1]);
        *(uint32_t*)&o[ro2 + dc] = packh2(oc[nt][2], oc[nt][3]);
    }
}

// ---------------- launch ----------------
extern "C" void kernel_launch(void* const* d_in, const int* in_sizes, int n_in,
                              void* d_out, int out_size)
{
    (void)in_sizes; (void)n_in; (void)out_size;
    const float* x      = (const float*)d_in[0];
    const float* g1     = (const float*)d_in[1];
    const float* b1     = (const float*)d_in[2];
    const float* w_qkv  = (const float*)d_in[3];
    const float* b_qkv  = (const float*)d_in[4];
    const float* w_proj = (const float*)d_in[5];
    const float* b_proj = (const float*)d_in[6];
    const float* g2     = (const float*)d_in[7];
    const float* b2     = (const float*)d_in[8];
    const float* w_fc1  = (const float*)d_in[9];
    const float* b_fc1  = (const float*)d_in[10];
    const float* w_fc2  = (const float*)d_in[11];
    const float* b_fc2  = (const float*)d_in[12];
    float* out = (float*)d_out;

    __half *ln, *big, *ow, *xo, *wqkv_h, *wproj_h, *wfc1_h, *wfc2_h;
    cudaGetSymbolAddress((void**)&ln,  g_ln);
    cudaGetSymbolAddress((void**)&big, g_big);
    cudaGetSymbolAddress((void**)&ow,  g_ow);
    cudaGetSymbolAddress((void**)&xo,  g_xo);
    cudaGetSymbolAddress((void**)&wqkv_h, g_wqkv_h);
    cudaGetSymbolAddress((void**)&wproj_h, g_wproj_h);
    cudaGetSymbolAddress((void**)&wfc1_h, g_wfc1_h);
    cudaGetSymbolAddress((void**)&wfc2_h, g_wfc2_h);

    const int SB = (int)GEMM_DYN;
    cudaFuncSetAttribute(gemm_kernel<192, 576, EPI_QKV>,  cudaFuncAttributeMaxDynamicSharedMemorySize, SB);
    cudaFuncSetAttribute(gemm_kernel<192, 192, EPI_PROJ>, cudaFuncAttributeMaxDynamicSharedMemorySize, SB);
    cudaFuncSetAttribute(gemm_kernel<192, 768, EPI_FC1>,  cudaFuncAttributeMaxDynamicSharedMemorySize, SB);
    cudaFuncSetAttribute(gemm_kernel<768, 192, EPI_FC2>,  cudaFuncAttributeMaxDynamicSharedMemorySize, SB);

    // 0. all weights fp32 -> fp16, one launch
    {
        int n0 = 192 * 576 / 4, n1 = 192 * 192 / 4, n2 = 192 * 768 / 4, n3 = 768 * 192 / 4;
        int total = n0 + n1 + n2 + n3;
        f2h_all_kernel<<<(total + 255) / 256, 256>>>(w_qkv, wqkv_h, n0, w_proj, wproj_h, n1,
                                                     w_fc1, wfc1_h, n2, w_fc2, wfc2_h, n3);
    }

    // 1. LN1 + window partition (fp32 in, fp16 out)
    ln_kernel<true, float><<<TOK / 8, 256>>>(x, g1, b1, ln);
    // 2. QKV GEMM: 6 column blocks of 96 (fp16 out)
    gemm_kernel<192, 576, EPI_QKV><<<dim3(6, TOK / GBM), NTHR, SB>>>(ln, wqkv_h, b_qkv, nullptr, big);
    // 3. attention per (head-pair, window): register softmax + ldmatrix
    attn_kernel<<<dim3(3, 4096), 256, ATTN_DYN>>>(big, ow);
    // 4. proj GEMM + window unpartition + residual x -> xo (fp16)
    gemm_kernel<192, 192, EPI_PROJ><<<dim3(2, TOK / GBM), NTHR, SB>>>(ow, wproj_h, b_proj, x, xo);
    // 5. LN2 (fp16 in, fp16 out)
    ln_kernel<false, __half><<<TOK / 8, 256>>>(xo, g2, b2, ln);
    // 6. FC1 GEMM + exact GELU (fp16 out)
    gemm_kernel<192, 768, EPI_FC1><<<dim3(8, TOK / GBM), NTHR, SB>>>(ln, wfc1_h, b_fc1, nullptr, big);
    // 7. FC2 GEMM + residual xo (fp16) -> out (fp32)
    gemm_kernel<768, 192, EPI_FC2><<<dim3(2, TOK / GBM), NTHR, SB>>>(big, wfc2_h, b_fc2, xo, out);
}